// round 7
// baseline (speedup 1.0000x reference)
#include <cuda_runtime.h>
#include <cuda_bf16.h>
#include <cstdint>

// ============================================================================
// ComplexConv2Deffangle via warp-level tf32 split MMA (mma.sync m16n8k8).
//   path0 (rot): depthwise 3x3 (w1^2/sum)  -> 1x1 (w2^2/sum)
//   path1 (abs): log(x+eps) -> depthwise (w1^2/rowsum) -> 1x1 (w2^2/rowsum) -> exp
// x: (32,2,64,64,64) f32, w1: (64,9), w2: (128,64) -> out: (32,2,128,62,62)
// Per block GEMM: D[128 och][128 n] = W[128][64] * V[64][128], 3-pass split tf32.
// ============================================================================

#define EPS 1e-6f
#define C_IN 64
#define C_OUT 128
#define HH 64
#define WW 64
#define OX 62
#define OY 62
#define LTOT (OX * OY)           // 3844

// smem byte offsets
#define OFF_WQ   0               // float4[2048]: W quads, one 32-ch chunk (32 KB)
#define OFF_BQ   32768           // float4[2048]: depthwise quads        (32 KB)
#define OFF_XIN  65536           // float[32][4][64]                     (32 KB)
#define OFF_W1S  98304           // float[64][9]                         (2.3 KB)
#define SMEM_TOTAL 100608
// trans (epilogue) reuses [0 .. 33792): float[128][66]

// Fragment-quad weights: per (path, chunk): 2048 float4, slot-swizzled.
// slot(kk,m,c4) = (kk*128+m)*4 + ((c4+m)&3); quad = {hi(c),lo(c),hi(c+4),lo(c+4)},
// c = cc*32 + kk*8 + c4.
__device__ float4 g_w2q[2][2][2048];
__device__ float  g_w1n[2][C_IN][9];

// ---------------------------------------------------------------------------
__device__ __forceinline__ float tf32r(float x) {
    uint32_t r;
    asm("cvt.rna.tf32.f32 %0, %1;" : "=r"(r) : "f"(x));
    return __uint_as_float(r);
}
__device__ __forceinline__ void mma_tf32(float* acc, uint32_t a0, uint32_t a1,
                                         uint32_t a2, uint32_t a3,
                                         uint32_t b0, uint32_t b1) {
    asm volatile(
        "mma.sync.aligned.m16n8k8.row.col.f32.tf32.tf32.f32 "
        "{%0,%1,%2,%3}, {%4,%5,%6,%7}, {%8,%9}, {%0,%1,%2,%3};"
        : "+f"(acc[0]), "+f"(acc[1]), "+f"(acc[2]), "+f"(acc[3])
        : "r"(a0), "r"(a1), "r"(a2), "r"(a3), "r"(b0), "r"(b1));
}

// ---------------------------------------------------------------------------
// Prep kernel: normalize weights, split tf32, pack fragment quads.
// ---------------------------------------------------------------------------
__global__ void prep_weights_kernel(const float* __restrict__ w1,
                                    const float* __restrict__ w2) {
    __shared__ float red[256];
    __shared__ float s1_sh, s2_sh;
    __shared__ float s1r[C_IN];
    __shared__ float s2r[C_OUT];
    int tid = threadIdx.x;

    float a = 0.f;
    for (int i = tid; i < C_IN * 9; i += 256) { float t = w1[i]; a += t * t; }
    red[tid] = a; __syncthreads();
    for (int s = 128; s > 0; s >>= 1) { if (tid < s) red[tid] += red[tid + s]; __syncthreads(); }
    if (tid == 0) s1_sh = red[0];
    __syncthreads();

    a = 0.f;
    for (int i = tid; i < C_OUT * C_IN; i += 256) { float t = w2[i]; a += t * t; }
    red[tid] = a; __syncthreads();
    for (int s = 128; s > 0; s >>= 1) { if (tid < s) red[tid] += red[tid + s]; __syncthreads(); }
    if (tid == 0) s2_sh = red[0];

    if (tid < C_IN) {
        float s = 0.f;
        for (int k = 0; k < 9; k++) { float t = w1[tid * 9 + k]; s += t * t; }
        s1r[tid] = s;
    }
    if (tid < C_OUT) {
        float s = 0.f;
        for (int c = 0; c < C_IN; c++) { float t = w2[tid * C_IN + c]; s += t * t; }
        s2r[tid] = s;
    }
    __syncthreads();

    float inv_s1 = 1.f / s1_sh;
    float inv_s2 = 1.f / s2_sh;

    for (int i = tid; i < C_IN * 9; i += 256) {
        int c = i / 9;
        float t = w1[i]; float t2 = t * t;
        ((float*)g_w1n[0])[i] = t2 * inv_s1;
        ((float*)g_w1n[1])[i] = t2 / s1r[c];
    }

    for (int j = tid; j < 2048; j += 256) {
        int kk = j >> 9;
        int m  = (j >> 2) & 127;
        int c4 = j & 3;
        int slot = (kk * 128 + m) * 4 + ((c4 + m) & 3);
        #pragma unroll
        for (int p = 0; p < 2; p++) {
            #pragma unroll
            for (int cc = 0; cc < 2; cc++) {
                int c = cc * 32 + kk * 8 + c4;
                float tA = w2[m * C_IN + c];
                float tB = w2[m * C_IN + c + 4];
                float gA = (p == 0) ? tA * tA * inv_s2 : tA * tA / s2r[m];
                float gB = (p == 0) ? tB * tB * inv_s2 : tB * tB / s2r[m];
                float hA = tf32r(gA), hB = tf32r(gB);
                g_w2q[p][cc][slot] = make_float4(hA, tf32r(gA - hA),
                                                 hB, tf32r(gB - hB));
            }
        }
    }
}

// ---------------------------------------------------------------------------
// Main kernel: grid (31 row-pairs, 32 batch, 2 path), 256 threads, 2 blk/SM.
// ---------------------------------------------------------------------------
__global__ __launch_bounds__(256, 2)
void cce_mma_kernel(const float* __restrict__ x, float* __restrict__ out) {
    extern __shared__ char smem[];
    float4* WQ   = (float4*)(smem + OFF_WQ);
    float4* BQ   = (float4*)(smem + OFF_BQ);
    float*  xin  = (float*)(smem + OFF_XIN);
    float*  w1s  = (float*)(smem + OFF_W1S);
    float*  trans = (float*)smem;            // epilogue reuse [128][66]

    const int tid  = threadIdx.x;
    const int warp = tid >> 5;
    const int lane = tid & 31;
    const int q    = lane >> 2;              // groupID
    const int r    = lane & 3;               // threadInGroup
    const int m0   = warp * 16;              // och tile base
    const int r0   = blockIdx.x * 2;
    const int b    = blockIdx.y;
    const int p    = blockIdx.z;

    for (int i = tid; i < C_IN * 9; i += 256) w1s[i] = ((const float*)g_w1n[p])[i];

    const float* xbase = x + (size_t)(b * 2 + p) * (C_IN * HH * WW) + r0 * WW;

    float acc[64];
    #pragma unroll
    for (int i = 0; i < 64; i++) acc[i] = 0.f;

    const int perm = (r + q) & 3;            // (c4 + n)&3 == (c4 + m)&3 == (r+q)&3

    #pragma unroll
    for (int cc = 0; cc < 2; cc++) {
        // ---- stage W quads + xin chunk ----
        const float4* wsrc = g_w2q[p][cc];
        #pragma unroll
        for (int i = 0; i < 8; i++) WQ[tid + i * 256] = wsrc[tid + i * 256];
        #pragma unroll
        for (int i = 0; i < 8; i++) {
            int idx = tid + i * 256;         // 0..2047 float4
            int cl = idx >> 6, qq = idx & 63;
            float4 v = ((const float4*)(xbase + (size_t)(cc * 32 + cl) * (HH * WW)))[qq];
            if (p == 1) {
                v.x = __logf(v.x + EPS); v.y = __logf(v.y + EPS);
                v.z = __logf(v.z + EPS); v.w = __logf(v.w + EPS);
            }
            ((float4*)(xin + cl * 256))[qq] = v;
        }
        __syncthreads();

        // ---- depthwise 3x3 -> hi/lo fragment quads in BQ ----
        #pragma unroll
        for (int i = 0; i < 8; i++) {
            int t  = tid + i * 256;          // 0..2047
            int kk = t >> 9;
            int c4 = (t >> 7) & 3;
            int n  = t & 127;
            int rl = n >> 6, l = n & 63;     // l>=62: garbage, never stored
            int cl = kk * 8 + c4;
            const float* xcA = xin + cl * 256 + rl * 64 + l;
            const float* xcB = xcA + 4 * 256;
            const float* wcA = w1s + (cc * 32 + cl) * 9;
            const float* wcB = wcA + 4 * 9;
            float aA = 0.f, aB = 0.f;
            #pragma unroll
            for (int rr = 0; rr < 3; rr++)
                #pragma unroll
                for (int jj = 0; jj < 3; jj++) {
                    aA = fmaf(xcA[rr * 64 + jj], wcA[rr * 3 + jj], aA);
                    aB = fmaf(xcB[rr * 64 + jj], wcB[rr * 3 + jj], aB);
                }
            float hA = tf32r(aA), hB = tf32r(aB);
            BQ[(kk * 128 + n) * 4 + ((c4 + n) & 3)] =
                make_float4(hA, tf32r(aA - hA), hB, tf32r(aB - hB));
        }
        __syncthreads();

        // ---- warp MMA: 4 k-steps x 16 n-tiles x 3 split passes ----
        #pragma unroll
        for (int kk = 0; kk < 4; kk++) {
            float4 A1 = WQ[(kk * 128 + m0 + q) * 4 + perm];      // a0h,a0l,a2h,a2l
            float4 A2 = WQ[(kk * 128 + m0 + q + 8) * 4 + perm];  // a1h,a1l,a3h,a3l
            uint32_t a0h = __float_as_uint(A1.x), a0l = __float_as_uint(A1.y);
            uint32_t a2h = __float_as_uint(A1.z), a2l = __float_as_uint(A1.w);
            uint32_t a1h = __float_as_uint(A2.x), a1l = __float_as_uint(A2.y);
            uint32_t a3h = __float_as_uint(A2.z), a3l = __float_as_uint(A2.w);
            const float4* bq = BQ + (kk * 128 + q) * 4 + perm;
            #pragma unroll
            for (int t = 0; t < 16; t++) {
                float4 B = bq[t * 32];                           // b0h,b0l,b1h,b1l
                uint32_t b0h = __float_as_uint(B.x), b0l = __float_as_uint(B.y);
                uint32_t b1h = __float_as_uint(B.z), b1l = __float_as_uint(B.w);
                mma_tf32(acc + t * 4, a0h, a1h, a2h, a3h, b0h, b1h);
                mma_tf32(acc + t * 4, a0h, a1h, a2h, a3h, b0l, b1l);
                mma_tf32(acc + t * 4, a0l, a1l, a2l, a3l, b0h, b1h);
            }
        }
        __syncthreads();
    }

    // ---- epilogue: fragment -> smem transpose -> coalesced stores ----
    // round rl covers n = rl*64 .. rl*64+63 == output row r0+rl, cols l=n&63.
    float* obase = out + (size_t)(b * 2 + p) * (C_OUT * LTOT) + (size_t)r0 * OY;
    #pragma unroll
    for (int rl = 0; rl < 2; rl++) {
        #pragma unroll
        for (int tt = 0; tt < 8; tt++) {
            int t = rl * 8 + tt;
            int col = tt * 8 + 2 * r;
            *(float2*)(trans + (m0 + q) * 66 + col)     = make_float2(acc[t*4+0], acc[t*4+1]);
            *(float2*)(trans + (m0 + q + 8) * 66 + col) = make_float2(acc[t*4+2], acc[t*4+3]);
        }
        __syncthreads();
        int l  = tid & 63;
        int mb = tid >> 6;
        if (l < OY) {
            float* orow = obase + rl * OY + l;
            #pragma unroll
            for (int i = 0; i < 32; i++) {
                int m = mb + i * 4;
                float v = trans[m * 66 + l];
                if (p == 1) v = __expf(v);
                orow[(size_t)m * LTOT] = v;
            }
        }
        __syncthreads();
    }
}

// ---------------------------------------------------------------------------
extern "C" void kernel_launch(void* const* d_in, const int* in_sizes, int n_in,
                              void* d_out, int out_size) {
    const float* x  = (const float*)d_in[0];
    const float* w1 = (const float*)d_in[1];
    const float* w2 = (const float*)d_in[2];
    float* out = (float*)d_out;

    prep_weights_kernel<<<1, 256>>>(w1, w2);

    cudaFuncSetAttribute(cce_mma_kernel,
                         cudaFuncAttributeMaxDynamicSharedMemorySize, SMEM_TOTAL);
    dim3 grid(OX / 2, 32, 2);                // (31, 32, 2)
    cce_mma_kernel<<<grid, 256, SMEM_TOTAL>>>(x, out);
}

// round 8
// speedup vs baseline: 1.3030x; 1.3030x over previous
#include <cuda_runtime.h>
#include <cuda_bf16.h>
#include <cstdint>

// ============================================================================
// ComplexConv2Deffangle via warp-level tf32 split MMA (mma.sync m16n8k8).
//   path0 (rot): depthwise 3x3 (w1^2/sum)  -> 1x1 (w2^2/sum)
//   path1 (abs): log(x+eps) -> depthwise (w1^2/rowsum) -> 1x1 (w2^2/rowsum) -> exp
// x: (32,2,64,64,64) f32, w1: (64,9), w2: (128,64) -> out: (32,2,128,62,62)
// Per block: D[128 och][128 n] = W[128][64] * V[64][128], 3-pass split tf32.
// n = 2 output rows x 64 cols (62 valid).
// ============================================================================

#define EPS 1e-6f
#define C_IN 64
#define C_OUT 128
#define HH 64
#define WW 64
#define OX 62
#define OY 62
#define LTOT (OX * OY)           // 3844

// smem byte offsets
#define OFF_BQ0  0               // float4[2048] depthwise quads chunk0 (32 KB)
#define OFF_XIN  32768           // float, ch stride 276, row stride 68 (35.3 KB)
#define OFF_BQ1  68096           // float4[2048] chunk1 (32 KB)
#define OFF_W1S  100864          // float[64][9]
#define SMEM_TOTAL 103168        // -> 2 blocks/SM

#define XCH 276                  // xin channel stride (floats)
#define XRW 68                   // xin row stride (floats)

// Fragment-quad weights: per (path, chunk): 2048 float4, slot-swizzled.
// quad(kk,m)[slot=(c4+m)&3] = {hi(c),lo(c),hi(c+4),lo(c+4)}, c = cc*32+kk*8+c4.
__device__ float4 g_w2q[2][2][2048];
__device__ float  g_w1n[2][C_IN][9];

// ---------------------------------------------------------------------------
__device__ __forceinline__ float tf32r(float x) {
    uint32_t r;
    asm("cvt.rna.tf32.f32 %0, %1;" : "=r"(r) : "f"(x));
    return __uint_as_float(r);
}
__device__ __forceinline__ void mma_tf32(float* acc, uint32_t a0, uint32_t a1,
                                         uint32_t a2, uint32_t a3,
                                         uint32_t b0, uint32_t b1) {
    asm volatile(
        "mma.sync.aligned.m16n8k8.row.col.f32.tf32.tf32.f32 "
        "{%0,%1,%2,%3}, {%4,%5,%6,%7}, {%8,%9}, {%0,%1,%2,%3};"
        : "+f"(acc[0]), "+f"(acc[1]), "+f"(acc[2]), "+f"(acc[3])
        : "r"(a0), "r"(a1), "r"(a2), "r"(a3), "r"(b0), "r"(b1));
}

// ---------------------------------------------------------------------------
// Prep kernel: normalize weights, split tf32, pack fragment quads.
// ---------------------------------------------------------------------------
__global__ void prep_weights_kernel(const float* __restrict__ w1,
                                    const float* __restrict__ w2) {
    __shared__ float red[256];
    __shared__ float s1_sh, s2_sh;
    __shared__ float s1r[C_IN];
    __shared__ float s2r[C_OUT];
    int tid = threadIdx.x;

    float a = 0.f;
    for (int i = tid; i < C_IN * 9; i += 256) { float t = w1[i]; a += t * t; }
    red[tid] = a; __syncthreads();
    for (int s = 128; s > 0; s >>= 1) { if (tid < s) red[tid] += red[tid + s]; __syncthreads(); }
    if (tid == 0) s1_sh = red[0];
    __syncthreads();

    a = 0.f;
    for (int i = tid; i < C_OUT * C_IN; i += 256) { float t = w2[i]; a += t * t; }
    red[tid] = a; __syncthreads();
    for (int s = 128; s > 0; s >>= 1) { if (tid < s) red[tid] += red[tid + s]; __syncthreads(); }
    if (tid == 0) s2_sh = red[0];

    if (tid < C_IN) {
        float s = 0.f;
        for (int k = 0; k < 9; k++) { float t = w1[tid * 9 + k]; s += t * t; }
        s1r[tid] = s;
    }
    if (tid < C_OUT) {
        float s = 0.f;
        for (int c = 0; c < C_IN; c++) { float t = w2[tid * C_IN + c]; s += t * t; }
        s2r[tid] = s;
    }
    __syncthreads();

    float inv_s1 = 1.f / s1_sh;
    float inv_s2 = 1.f / s2_sh;

    for (int i = tid; i < C_IN * 9; i += 256) {
        int c = i / 9;
        float t = w1[i]; float t2 = t * t;
        ((float*)g_w1n[0])[i] = t2 * inv_s1;
        ((float*)g_w1n[1])[i] = t2 / s1r[c];
    }

    for (int j = tid; j < 2048; j += 256) {
        int kk = j >> 9;
        int m  = (j >> 2) & 127;
        int c4 = j & 3;
        int slot = (kk * 128 + m) * 4 + ((c4 + m) & 3);
        #pragma unroll
        for (int p = 0; p < 2; p++) {
            #pragma unroll
            for (int cc = 0; cc < 2; cc++) {
                int c = cc * 32 + kk * 8 + c4;
                float tA = w2[m * C_IN + c];
                float tB = w2[m * C_IN + c + 4];
                float gA = (p == 0) ? tA * tA * inv_s2 : tA * tA / s2r[m];
                float gB = (p == 0) ? tB * tB * inv_s2 : tB * tB / s2r[m];
                float hA = tf32r(gA), hB = tf32r(gB);
                g_w2q[p][cc][slot] = make_float4(hA, tf32r(gA - hA),
                                                 hB, tf32r(gB - hB));
            }
        }
    }
}

// ---------------------------------------------------------------------------
// Main kernel: grid (31 row-pairs, 32 batch, 2 path), 256 threads, 2 blk/SM.
// ---------------------------------------------------------------------------
__global__ __launch_bounds__(256, 2)
void cce_mma_kernel(const float* __restrict__ x, float* __restrict__ out) {
    extern __shared__ char smem[];
    float*  xin = (float*)(smem + OFF_XIN);
    float*  w1s = (float*)(smem + OFF_W1S);

    const int tid  = threadIdx.x;
    const int warp = tid >> 5;
    const int lane = tid & 31;
    const int q    = lane >> 2;              // groupID
    const int r    = lane & 3;               // threadInGroup
    const int m0   = warp * 16;              // och tile base
    const int r0   = blockIdx.x * 2;
    const int b    = blockIdx.y;
    const int p    = blockIdx.z;
    const int perm = (r + q) & 3;

    for (int i = tid; i < C_IN * 9; i += 256) w1s[i] = ((const float*)g_w1n[p])[i];

    const float* xbase = x + (size_t)(b * 2 + p) * (C_IN * HH * WW) + r0 * WW;

    // depthwise work-item decomposition (fixed per thread)
    const int c4  = tid & 3;
    const int kk0 = (tid >> 2) & 3;
    const int nb  = tid >> 4;                // 0..15
    const int n0  = nb * 8;
    const int rl0 = n0 >> 6;
    const int l0  = n0 & 63;
    const int chA = kk0 * 8 + c4;            // chB = chA + 4
    const int l2  = (l0 < 56) ? (l0 + 8) : l0;   // clamped 3rd float4

    // ========== phase 1: stage + depthwise, both chunks ==========
    #pragma unroll
    for (int cc = 0; cc < 2; cc++) {
        float4* BQ = (float4*)(smem + (cc ? OFF_BQ1 : OFF_BQ0));

        // stage 32 ch x 4 rows into padded xin
        #pragma unroll
        for (int i = 0; i < 8; i++) {
            int idx = tid + i * 256;         // 0..2047 float4
            int cl = idx >> 6, qq = idx & 63;
            int rr = qq >> 4, lq = qq & 15;
            float4 v = ((const float4*)(xbase + (size_t)(cc * 32 + cl) * (HH * WW)))[qq];
            if (p == 1) {
                v.x = __logf(v.x + EPS); v.y = __logf(v.y + EPS);
                v.z = __logf(v.z + EPS); v.w = __logf(v.w + EPS);
            }
            ((float4*)(xin + cl * XCH + rr * XRW))[lq] = v;
        }
        __syncthreads();

        // depthwise: 8 cols x 2 channels per thread, float4 reads
        float aA[8], aB[8];
        #pragma unroll
        for (int i = 0; i < 8; i++) { aA[i] = 0.f; aB[i] = 0.f; }

        #pragma unroll
        for (int ch2 = 0; ch2 < 2; ch2++) {
            int ch = chA + ch2 * 4;
            float* acc8 = ch2 ? aB : aA;
            const float* wc = w1s + (cc * 32 + ch) * 9;
            #pragma unroll
            for (int rr = 0; rr < 3; rr++) {
                const float* xr = xin + ch * XCH + (rl0 + rr) * XRW;
                float4 u0 = *(const float4*)(xr + l0);
                float4 u1 = *(const float4*)(xr + l0 + 4);
                float4 u2 = *(const float4*)(xr + l2);
                float f[12] = {u0.x,u0.y,u0.z,u0.w, u1.x,u1.y,u1.z,u1.w,
                               u2.x,u2.y,u2.z,u2.w};
                float w0 = wc[rr * 3 + 0], w1v = wc[rr * 3 + 1], w2v = wc[rr * 3 + 2];
                #pragma unroll
                for (int ci = 0; ci < 8; ci++) {
                    float s = acc8[ci];
                    s = fmaf(f[ci],     w0,  s);
                    s = fmaf(f[ci + 1], w1v, s);
                    s = fmaf(f[ci + 2], w2v, s);
                    acc8[ci] = s;
                }
            }
        }
        // split + store quads
        #pragma unroll
        for (int ci = 0; ci < 8; ci++) {
            int n = n0 + ci;
            float hA = tf32r(aA[ci]);
            float hB = tf32r(aB[ci]);
            BQ[(kk0 * 128 + n) * 4 + ((c4 + n) & 3)] =
                make_float4(hA, tf32r(aA[ci] - hA), hB, tf32r(aB[ci] - hB));
        }
        __syncthreads();
    }

    // ========== phase 2: MMA over both chunks ==========
    float acc[64];
    #pragma unroll
    for (int i = 0; i < 64; i++) acc[i] = 0.f;

    #pragma unroll
    for (int cc = 0; cc < 2; cc++) {
        const float4* BQ = (const float4*)(smem + (cc ? OFF_BQ1 : OFF_BQ0));
        const float4* wg = g_w2q[p][cc];
        #pragma unroll
        for (int kk = 0; kk < 4; kk++) {
            float4 A1 = wg[(kk * 128 + m0 + q) * 4 + perm];      // a0h,a0l,a2h,a2l
            float4 A2 = wg[(kk * 128 + m0 + q + 8) * 4 + perm];  // a1h,a1l,a3h,a3l
            uint32_t a0h = __float_as_uint(A1.x), a0l = __float_as_uint(A1.y);
            uint32_t a2h = __float_as_uint(A1.z), a2l = __float_as_uint(A1.w);
            uint32_t a1h = __float_as_uint(A2.x), a1l = __float_as_uint(A2.y);
            uint32_t a3h = __float_as_uint(A2.z), a3l = __float_as_uint(A2.w);
            const float4* bq = BQ + (kk * 128 + q) * 4 + perm;
            #pragma unroll
            for (int t = 0; t < 16; t++) {
                float4 B = bq[t * 32];                           // b0h,b0l,b1h,b1l
                uint32_t b0h = __float_as_uint(B.x), b0l = __float_as_uint(B.y);
                uint32_t b1h = __float_as_uint(B.z), b1l = __float_as_uint(B.w);
                mma_tf32(acc + t * 4, a0h, a1h, a2h, a3h, b0h, b1h);
                mma_tf32(acc + t * 4, a0h, a1h, a2h, a3h, b0l, b1l);
                mma_tf32(acc + t * 4, a0l, a1l, a2l, a3l, b0h, b1h);
            }
        }
    }

    // ========== phase 3: direct sector-coalesced stores ==========
    // tile t: rows (m0+q, m0+q+8), out-row rl=t>>3, cols colb=(t&7)*8+2r (+1)
    float* obase = out + (size_t)(b * 2 + p) * (C_OUT * LTOT) + (size_t)r0 * OY;
    #pragma unroll
    for (int t = 0; t < 16; t++) {
        int colb = (t & 7) * 8 + 2 * r;
        if (colb < OY) {
            int rl = t >> 3;
            float2 v0 = make_float2(acc[t * 4 + 0], acc[t * 4 + 1]);
            float2 v1 = make_float2(acc[t * 4 + 2], acc[t * 4 + 3]);
            if (p == 1) {
                v0.x = __expf(v0.x); v0.y = __expf(v0.y);
                v1.x = __expf(v1.x); v1.y = __expf(v1.y);
            }
            float* addr = obase + rl * OY + colb;
            *(float2*)(addr + (size_t)(m0 + q) * LTOT)     = v0;
            *(float2*)(addr + (size_t)(m0 + q + 8) * LTOT) = v1;
        }
    }
}

// ---------------------------------------------------------------------------
extern "C" void kernel_launch(void* const* d_in, const int* in_sizes, int n_in,
                              void* d_out, int out_size) {
    const float* x  = (const float*)d_in[0];
    const float* w1 = (const float*)d_in[1];
    const float* w2 = (const float*)d_in[2];
    float* out = (float*)d_out;

    prep_weights_kernel<<<1, 256>>>(w1, w2);

    cudaFuncSetAttribute(cce_mma_kernel,
                         cudaFuncAttributeMaxDynamicSharedMemorySize, SMEM_TOTAL);
    dim3 grid(OX / 2, 32, 2);                // (31, 32, 2)
    cce_mma_kernel<<<grid, 256, SMEM_TOTAL>>>(x, out);
}

// round 9
// speedup vs baseline: 1.6318x; 1.2523x over previous
#include <cuda_runtime.h>
#include <cuda_bf16.h>
#include <cstdint>

// ============================================================================
// ComplexConv2Deffangle via warp-level tf32 split MMA (mma.sync m16n8k8),
// cp.async-pipelined staging, conflict-free smem layouts.
//   path0 (rot): depthwise 3x3 (w1^2/sum)  -> 1x1 (w2^2/sum)
//   path1 (abs): log(x+eps) -> depthwise (w1^2/rowsum) -> 1x1 (w2^2/rowsum) -> exp
// x: (32,2,64,64,64) f32, w1: (64,9), w2: (128,64) -> out: (32,2,128,62,62)
// Per block: D[128 och][128 n] = W[128][64] * V[64][128], 3-pass split tf32.
// ============================================================================

#define EPS 1e-6f
#define C_IN 64
#define C_OUT 128
#define HH 64
#define WW 64
#define OX 62
#define OY 62
#define LTOT (OX * OY)           // 3844

#define XCH 300                  // xin channel stride (floats)
#define XRW 68                   // xin row stride (floats)

// smem byte offsets
#define OFF_BQ   0               // float4[2056] quads (+kk shift)    32,896 B
#define OFF_X0   32896           // xin chunk0: 9596 floats           38,384 B
#define OFF_X1   71280           // xin chunk1                        38,384 B
#define OFF_W1S  109664          // float[64][9]                       2,304 B
#define SMEM_TOTAL 111968        // -> 2 blocks/SM

// Fragment-quad weights: per (path, chunk): 2048 float4.
// quad(kk,m)[slot=(c4+m)&3] = {hi(c),lo(c),hi(c+4),lo(c+4)}, c = cc*32+kk*8+c4.
__device__ float4 g_w2q[2][2][2048];
__device__ float  g_w1n[2][C_IN][9];

// ---------------------------------------------------------------------------
__device__ __forceinline__ uint32_t smem_u32(const void* p) {
    uint32_t a;
    asm("{ .reg .u64 t; cvta.to.shared.u64 t, %1; cvt.u32.u64 %0, t; }"
        : "=r"(a) : "l"(p));
    return a;
}
__device__ __forceinline__ float tf32r(float x) {
    uint32_t r;
    asm("cvt.rna.tf32.f32 %0, %1;" : "=r"(r) : "f"(x));
    return __uint_as_float(r);
}
__device__ __forceinline__ float trunc13(float a) {       // tf32 hi via mask
    return __uint_as_float(__float_as_uint(a) & 0xFFFFE000u);
}
__device__ __forceinline__ void mma_tf32(float* acc, uint32_t a0, uint32_t a1,
                                         uint32_t a2, uint32_t a3,
                                         uint32_t b0, uint32_t b1) {
    asm volatile(
        "mma.sync.aligned.m16n8k8.row.col.f32.tf32.tf32.f32 "
        "{%0,%1,%2,%3}, {%4,%5,%6,%7}, {%8,%9}, {%0,%1,%2,%3};"
        : "+f"(acc[0]), "+f"(acc[1]), "+f"(acc[2]), "+f"(acc[3])
        : "r"(a0), "r"(a1), "r"(a2), "r"(a3), "r"(b0), "r"(b1));
}
__device__ __forceinline__ void cp16(uint32_t dst, const void* src) {
    asm volatile("cp.async.cg.shared.global [%0], [%1], 16;"
                 :: "r"(dst), "l"(src) : "memory");
}
#define CP_COMMIT() asm volatile("cp.async.commit_group;" ::: "memory")
#define CP_WAIT(n)  asm volatile("cp.async.wait_group %0;" :: "n"(n) : "memory")

// xin addressing: float offset of (channel cl in 0..31, row rr, col f)
__device__ __forceinline__ int xoff(int cl, int rr, int f) {
    return cl * XCH + (cl >> 3) * 8 + rr * XRW + f;
}

// ---------------------------------------------------------------------------
// Prep kernel: normalize weights, split tf32, pack fragment quads.
// ---------------------------------------------------------------------------
__global__ void prep_weights_kernel(const float* __restrict__ w1,
                                    const float* __restrict__ w2) {
    __shared__ float red[256];
    __shared__ float s1_sh, s2_sh;
    __shared__ float s1r[C_IN];
    __shared__ float s2r[C_OUT];
    int tid = threadIdx.x;

    float a = 0.f;
    for (int i = tid; i < C_IN * 9; i += 256) { float t = w1[i]; a += t * t; }
    red[tid] = a; __syncthreads();
    for (int s = 128; s > 0; s >>= 1) { if (tid < s) red[tid] += red[tid + s]; __syncthreads(); }
    if (tid == 0) s1_sh = red[0];
    __syncthreads();

    a = 0.f;
    for (int i = tid; i < C_OUT * C_IN; i += 256) { float t = w2[i]; a += t * t; }
    red[tid] = a; __syncthreads();
    for (int s = 128; s > 0; s >>= 1) { if (tid < s) red[tid] += red[tid + s]; __syncthreads(); }
    if (tid == 0) s2_sh = red[0];

    if (tid < C_IN) {
        float s = 0.f;
        for (int k = 0; k < 9; k++) { float t = w1[tid * 9 + k]; s += t * t; }
        s1r[tid] = s;
    }
    if (tid < C_OUT) {
        float s = 0.f;
        for (int c = 0; c < C_IN; c++) { float t = w2[tid * C_IN + c]; s += t * t; }
        s2r[tid] = s;
    }
    __syncthreads();

    float inv_s1 = 1.f / s1_sh;
    float inv_s2 = 1.f / s2_sh;

    for (int i = tid; i < C_IN * 9; i += 256) {
        int c = i / 9;
        float t = w1[i]; float t2 = t * t;
        ((float*)g_w1n[0])[i] = t2 * inv_s1;
        ((float*)g_w1n[1])[i] = t2 / s1r[c];
    }

    for (int j = tid; j < 2048; j += 256) {
        int kk = j >> 9;
        int m  = (j >> 2) & 127;
        int c4 = j & 3;
        int slot = (kk * 128 + m) * 4 + ((c4 + m) & 3);
        #pragma unroll
        for (int p = 0; p < 2; p++) {
            #pragma unroll
            for (int cc = 0; cc < 2; cc++) {
                int c = cc * 32 + kk * 8 + c4;
                float tA = w2[m * C_IN + c];
                float tB = w2[m * C_IN + c + 4];
                float gA = (p == 0) ? tA * tA * inv_s2 : tA * tA / s2r[m];
                float gB = (p == 0) ? tB * tB * inv_s2 : tB * tB / s2r[m];
                float hA = tf32r(gA), hB = tf32r(gB);
                g_w2q[p][cc][slot] = make_float4(hA, tf32r(gA - hA),
                                                 hB, tf32r(gB - hB));
            }
        }
    }
}

// ---------------------------------------------------------------------------
// Main kernel: grid (31 row-pairs, 32 batch, 2 path), 256 threads, 2 blk/SM.
// ---------------------------------------------------------------------------
__global__ __launch_bounds__(256, 2)
void cce_mma_kernel(const float* __restrict__ x, float* __restrict__ out) {
    extern __shared__ char smem[];
    const uint32_t sb = smem_u32(smem);
    float4* BQ  = (float4*)(smem + OFF_BQ);
    float*  w1s = (float*)(smem + OFF_W1S);

    const int tid  = threadIdx.x;
    const int warp = tid >> 5;
    const int lane = tid & 31;
    const int q    = lane >> 2;              // groupID
    const int r    = lane & 3;               // threadInGroup
    const int m0   = warp * 16;              // och tile base
    const int r0   = blockIdx.x * 2;
    const int b    = blockIdx.y;
    const int p    = blockIdx.z;
    const int perm = (r + q) & 3;

    const float* xbase = x + (size_t)(b * 2 + p) * (C_IN * HH * WW) + r0 * WW;

    // ---- issue cp.async for both chunks up front ----
    #pragma unroll
    for (int cc = 0; cc < 2; cc++) {
        const uint32_t xo = sb + (cc ? OFF_X1 : OFF_X0);
        const float* xc = xbase + (size_t)(cc * 32) * (HH * WW);
        #pragma unroll
        for (int i = 0; i < 8; i++) {
            int idx = tid + i * 256;         // 0..2047 float4
            int cl = idx >> 6, qq = idx & 63;
            cp16(xo + (uint32_t)xoff(cl, qq >> 4, (qq & 15) * 4) * 4,
                 xc + (size_t)cl * (HH * WW) + qq * 4);
        }
        CP_COMMIT();
    }
    for (int i = tid; i < C_IN * 9; i += 256) w1s[i] = ((const float*)g_w1n[p])[i];

    // depthwise work decomposition: thread -> channels {chA, chA+4}, 8 cols
    const int c4  = tid & 3;
    const int kk0 = (tid >> 2) & 3;
    const int nb  = tid >> 4;                // 0..15
    const int n0  = nb * 8;
    const int rl0 = n0 >> 6;
    const int l0  = n0 & 63;
    const int chA = c4 * 8 + kk0;            // chB = chA + 4
    const int l2  = (l0 < 56) ? (l0 + 8) : l0;

    float acc[64];
    #pragma unroll
    for (int i = 0; i < 64; i++) acc[i] = 0.f;

    #pragma unroll
    for (int cc = 0; cc < 2; cc++) {
        float* xin = (float*)(smem + (cc ? OFF_X1 : OFF_X0));

        if (cc == 0) { CP_WAIT(1); } else { CP_WAIT(0); }
        __syncthreads();                     // staged data visible block-wide
                                             // (cc==1: also guards BQ rewrite)
        if (p == 1) {
            // in-place log transform
            #pragma unroll
            for (int i = 0; i < 8; i++) {
                int idx = tid + i * 256;
                int cl = idx >> 6, qq = idx & 63;
                float* pp = xin + xoff(cl, qq >> 4, (qq & 15) * 4);
                float4 v = *(float4*)pp;
                v.x = __logf(v.x + EPS); v.y = __logf(v.y + EPS);
                v.z = __logf(v.z + EPS); v.w = __logf(v.w + EPS);
                *(float4*)pp = v;
            }
            __syncthreads();
        }

        // ---- depthwise 3x3 -> hi/lo quads (conflict-free layout) ----
        float aA[8], aB[8];
        #pragma unroll
        for (int i = 0; i < 8; i++) { aA[i] = 0.f; aB[i] = 0.f; }
        #pragma unroll
        for (int ch2 = 0; ch2 < 2; ch2++) {
            int ch = chA + ch2 * 4;
            float* acc8 = ch2 ? aB : aA;
            const float* wc = w1s + (cc * 32 + ch) * 9;
            #pragma unroll
            for (int rr = 0; rr < 3; rr++) {
                const float* xr = xin + xoff(ch, rl0 + rr, 0);
                float4 u0 = *(const float4*)(xr + l0);
                float4 u1 = *(const float4*)(xr + l0 + 4);
                float4 u2 = *(const float4*)(xr + l2);
                float f[12] = {u0.x,u0.y,u0.z,u0.w, u1.x,u1.y,u1.z,u1.w,
                               u2.x,u2.y,u2.z,u2.w};
                float w0 = wc[rr * 3 + 0], w1v = wc[rr * 3 + 1], w2v = wc[rr * 3 + 2];
                #pragma unroll
                for (int ci = 0; ci < 8; ci++) {
                    float s = acc8[ci];
                    s = fmaf(f[ci],     w0,  s);
                    s = fmaf(f[ci + 1], w1v, s);
                    s = fmaf(f[ci + 2], w2v, s);
                    acc8[ci] = s;
                }
            }
        }
        // split (exact truncation) + store quads; writer quad kk = c4, slot c4' = kk0
        {
            const int qbase = (c4 << 9) + (c4 << 1);  // kk*512 + 2*kk, kk=c4
            #pragma unroll
            for (int ci = 0; ci < 8; ci++) {
                int n = n0 + ci;
                float hA = trunc13(aA[ci]);
                float hB = trunc13(aB[ci]);
                BQ[qbase + (n << 2) + ((kk0 + n) & 3)] =
                    make_float4(hA, aA[ci] - hA, hB, aB[ci] - hB);
            }
        }
        __syncthreads();

        // ---- warp MMA: 4 k-steps x 16 n-tiles x 3 split passes ----
        const float4* wg = g_w2q[p][cc];
        #pragma unroll
        for (int kk = 0; kk < 4; kk++) {
            float4 A1 = wg[(kk * 128 + m0 + q) * 4 + perm];      // a0h,a0l,a2h,a2l
            float4 A2 = wg[(kk * 128 + m0 + q + 8) * 4 + perm];  // a1h,a1l,a3h,a3l
            uint32_t a0h = __float_as_uint(A1.x), a0l = __float_as_uint(A1.y);
            uint32_t a2h = __float_as_uint(A1.z), a2l = __float_as_uint(A1.w);
            uint32_t a1h = __float_as_uint(A2.x), a1l = __float_as_uint(A2.y);
            uint32_t a3h = __float_as_uint(A2.z), a3l = __float_as_uint(A2.w);
            const float4* bq = BQ + (kk << 9) + (kk << 1) + (q << 2) + perm;
            #pragma unroll
            for (int t = 0; t < 16; t++) {
                float4 B = bq[t * 32];                           // b0h,b0l,b1h,b1l
                uint32_t b0h = __float_as_uint(B.x), b0l = __float_as_uint(B.y);
                uint32_t b1h = __float_as_uint(B.z), b1l = __float_as_uint(B.w);
                mma_tf32(acc + t * 4, a0h, a1h, a2h, a3h, b0h, b1h);
                mma_tf32(acc + t * 4, a0h, a1h, a2h, a3h, b0l, b1l);
                mma_tf32(acc + t * 4, a0l, a1l, a2l, a3l, b0h, b1h);
            }
        }
    }

    // ---- epilogue: direct sector-coalesced stores ----
    float* obase = out + (size_t)(b * 2 + p) * (C_OUT * LTOT) + (size_t)r0 * OY;
    #pragma unroll
    for (int t = 0; t < 16; t++) {
        int colb = (t & 7) * 8 + 2 * r;
        if (colb < OY) {
            int rl = t >> 3;
            float2 v0 = make_float2(acc[t * 4 + 0], acc[t * 4 + 1]);
            float2 v1 = make_float2(acc[t * 4 + 2], acc[t * 4 + 3]);
            if (p == 1) {
                v0.x = __expf(v0.x); v0.y = __expf(v0.y);
                v1.x = __expf(v1.x); v1.y = __expf(v1.y);
            }
            float* addr = obase + rl * OY + colb;
            *(float2*)(addr + (size_t)(m0 + q) * LTOT)     = v0;
            *(float2*)(addr + (size_t)(m0 + q + 8) * LTOT) = v1;
        }
    }
}

// ---------------------------------------------------------------------------
extern "C" void kernel_launch(void* const* d_in, const int* in_sizes, int n_in,
                              void* d_out, int out_size) {
    const float* x  = (const float*)d_in[0];
    const float* w1 = (const float*)d_in[1];
    const float* w2 = (const float*)d_in[2];
    float* out = (float*)d_out;

    prep_weights_kernel<<<1, 256>>>(w1, w2);

    cudaFuncSetAttribute(cce_mma_kernel,
                         cudaFuncAttributeMaxDynamicSharedMemorySize, SMEM_TOTAL);
    dim3 grid(OX / 2, 32, 2);                // (31, 32, 2)
    cce_mma_kernel<<<grid, 256, SMEM_TOTAL>>>(x, out);
}

// round 10
// speedup vs baseline: 1.9787x; 1.2126x over previous
#include <cuda_runtime.h>
#include <cuda_bf16.h>
#include <cstdint>

// ============================================================================
// ComplexConv2Deffangle via warp-level bf16 3-term split MMA (mma.sync
// m16n8k16.bf16), cp.async staging, conflict-free smem layouts.
//   path0 (rot): depthwise 3x3 (w1^2/sum)  -> 1x1 (w2^2/sum)
//   path1 (abs): log(x+eps) -> depthwise (w1^2/rowsum) -> 1x1 (w2^2/rowsum) -> exp
// x: (32,2,64,64,64) f32, w1: (64,9), w2: (128,64) -> out: (32,2,128,62,62)
// Per block: D[128 och][128 n] = W[128][64] * V[64][128]; split v = hi + lo
// (bf16 each), D = Wh*Vh + Wh*Vl + Wl*Vh  (lo*lo term ~2^-18, dropped).
// ============================================================================

#define EPS 1e-6f
#define C_IN 64
#define C_OUT 128
#define HH 64
#define WW 64
#define OX 62
#define OY 62
#define LTOT (OX * OY)           // 3844

#define XCH 300                  // xin channel stride (floats)
#define XRW 68                   // xin row stride (floats)

// smem byte offsets
#define OFF_BQ   0               // uint4[1032]: B quads (+4/kk shift)  16,512 B
#define OFF_X0   16512           // xin chunk0: 9572 floats             38,336 B
#define OFF_X1   54848           // xin chunk1                          38,336 B
#define OFF_W1S  93184           // float[64][9]                         2,304 B
#define SMEM_TOTAL 95488         // -> 2 blocks/SM

// A fragments pre-packed for m16n8k16.bf16, hi/lo interleaved:
// flat[( ((p*2+cc)*2+kk)*8 + warp)*32 + lane ][hl]  (float4 each)
__device__ float4 g_w2b[2][2][2][8][32][2];
__device__ float  g_w1n[2][C_IN][9];

// ---------------------------------------------------------------------------
__device__ __forceinline__ uint32_t smem_u32(const void* p) {
    uint32_t a;
    asm("{ .reg .u64 t; cvta.to.shared.u64 t, %1; cvt.u32.u64 %0, t; }"
        : "=r"(a) : "l"(p));
    return a;
}
// pack {upper=hi_e, lower=lo_e} as bf16x2
__device__ __forceinline__ uint32_t pack_bf(float lo_e, float hi_e) {
    uint32_t d;
    asm("cvt.rn.bf16x2.f32 %0, %1, %2;" : "=r"(d) : "f"(hi_e), "f"(lo_e));
    return d;
}
__device__ __forceinline__ float ubf_lo(uint32_t h) { return __uint_as_float(h << 16); }
__device__ __forceinline__ float ubf_hi(uint32_t h) { return __uint_as_float(h & 0xFFFF0000u); }
__device__ __forceinline__ float bf16rn(float x) {
    uint32_t d;
    asm("cvt.rn.bf16x2.f32 %0, %1, %1;" : "=r"(d) : "f"(x));
    return __uint_as_float(d << 16);
}
__device__ __forceinline__ void mma_bf16(float* acc, uint32_t a0, uint32_t a1,
                                         uint32_t a2, uint32_t a3,
                                         uint32_t b0, uint32_t b1) {
    asm volatile(
        "mma.sync.aligned.m16n8k16.row.col.f32.bf16.bf16.f32 "
        "{%0,%1,%2,%3}, {%4,%5,%6,%7}, {%8,%9}, {%0,%1,%2,%3};"
        : "+f"(acc[0]), "+f"(acc[1]), "+f"(acc[2]), "+f"(acc[3])
        : "r"(a0), "r"(a1), "r"(a2), "r"(a3), "r"(b0), "r"(b1));
}
__device__ __forceinline__ void cp16(uint32_t dst, const void* src) {
    asm volatile("cp.async.cg.shared.global [%0], [%1], 16;"
                 :: "r"(dst), "l"(src) : "memory");
}
#define CP_COMMIT() asm volatile("cp.async.commit_group;" ::: "memory")
#define CP_WAIT(n)  asm volatile("cp.async.wait_group %0;" :: "n"(n) : "memory")

// xin addressing: float offset of (channel cl in 0..31, row rr, col f)
__device__ __forceinline__ int xoff(int cl, int rr, int f) {
    return cl * XCH + (cl >> 4) * 4 + rr * XRW + f;
}

// ---------------------------------------------------------------------------
// Prep kernel: normalize weights, bf16-split, pack mma A fragments.
// ---------------------------------------------------------------------------
__global__ void prep_weights_kernel(const float* __restrict__ w1,
                                    const float* __restrict__ w2) {
    __shared__ float red[256];
    __shared__ float s1_sh, s2_sh;
    __shared__ float s1r[C_IN];
    __shared__ float s2r[C_OUT];
    int tid = threadIdx.x;

    float a = 0.f;
    for (int i = tid; i < C_IN * 9; i += 256) { float t = w1[i]; a += t * t; }
    red[tid] = a; __syncthreads();
    for (int s = 128; s > 0; s >>= 1) { if (tid < s) red[tid] += red[tid + s]; __syncthreads(); }
    if (tid == 0) s1_sh = red[0];
    __syncthreads();

    a = 0.f;
    for (int i = tid; i < C_OUT * C_IN; i += 256) { float t = w2[i]; a += t * t; }
    red[tid] = a; __syncthreads();
    for (int s = 128; s > 0; s >>= 1) { if (tid < s) red[tid] += red[tid + s]; __syncthreads(); }
    if (tid == 0) s2_sh = red[0];

    if (tid < C_IN) {
        float s = 0.f;
        for (int k = 0; k < 9; k++) { float t = w1[tid * 9 + k]; s += t * t; }
        s1r[tid] = s;
    }
    if (tid < C_OUT) {
        float s = 0.f;
        for (int c = 0; c < C_IN; c++) { float t = w2[tid * C_IN + c]; s += t * t; }
        s2r[tid] = s;
    }
    __syncthreads();

    float inv_s1 = 1.f / s1_sh;
    float inv_s2 = 1.f / s2_sh;

    for (int i = tid; i < C_IN * 9; i += 256) {
        int c = i / 9;
        float t = w1[i]; float t2 = t * t;
        ((float*)g_w1n[0])[i] = t2 * inv_s1;
        ((float*)g_w1n[1])[i] = t2 / s1r[c];
    }

    // A fragments: j indexes (p, cc, kk, warp, lane)
    float4* flat = (float4*)g_w2b;
    for (int j = tid; j < 2048; j += 256) {
        int lane = j & 31;
        int wq   = (j >> 5) & 7;
        int kk   = (j >> 8) & 1;
        int cc   = (j >> 9) & 1;
        int p    = j >> 10;
        int qq = lane >> 2, rr2 = lane & 3;
        int cb = cc * 32 + kk * 16 + 2 * rr2;
        int ms[2] = {wq * 16 + qq, wq * 16 + qq + 8};
        uint32_t ah[4], al[4];
        #pragma unroll
        for (int i = 0; i < 4; i++) {
            int m  = ms[i & 1];
            int c0 = cb + (i >> 1) * 8;
            float t0 = w2[m * C_IN + c0];
            float t1 = w2[m * C_IN + c0 + 1];
            float v0 = (p == 0) ? t0 * t0 * inv_s2 : t0 * t0 / s2r[m];
            float v1 = (p == 0) ? t1 * t1 * inv_s2 : t1 * t1 / s2r[m];
            float h0 = bf16rn(v0), h1 = bf16rn(v1);
            ah[i] = pack_bf(h0, h1);           // lower = k even
            al[i] = pack_bf(v0 - h0, v1 - h1);
        }
        flat[j * 2 + 0] = make_float4(__uint_as_float(ah[0]), __uint_as_float(ah[1]),
                                      __uint_as_float(ah[2]), __uint_as_float(ah[3]));
        flat[j * 2 + 1] = make_float4(__uint_as_float(al[0]), __uint_as_float(al[1]),
                                      __uint_as_float(al[2]), __uint_as_float(al[3]));
    }
}

// ---------------------------------------------------------------------------
// Main kernel: grid (31 row-pairs, 32 batch, 2 path), 256 threads, 2 blk/SM.
// ---------------------------------------------------------------------------
__global__ __launch_bounds__(256, 2)
void cce_mma_kernel(const float* __restrict__ x, float* __restrict__ out) {
    extern __shared__ char smem[];
    const uint32_t sb = smem_u32(smem);
    uint4*  BQ  = (uint4*)(smem + OFF_BQ);
    float*  w1s = (float*)(smem + OFF_W1S);

    const int tid  = threadIdx.x;
    const int warp = tid >> 5;
    const int lane = tid & 31;
    const int q    = lane >> 2;              // groupID
    const int r    = lane & 3;               // threadInGroup
    const int m0   = warp * 16;              // och tile base
    const int r0   = blockIdx.x * 2;
    const int b    = blockIdx.y;
    const int p    = blockIdx.z;

    const float* xbase = x + (size_t)(b * 2 + p) * (C_IN * HH * WW) + r0 * WW;

    // ---- issue cp.async for both chunks up front ----
    #pragma unroll
    for (int cc = 0; cc < 2; cc++) {
        const uint32_t xo = sb + (cc ? OFF_X1 : OFF_X0);
        const float* xc = xbase + (size_t)(cc * 32) * (HH * WW);
        #pragma unroll
        for (int i = 0; i < 8; i++) {
            int idx = tid + i * 256;         // 0..2047 float4
            int cl = idx >> 6, qq = idx & 63;
            cp16(xo + (uint32_t)xoff(cl, qq >> 4, (qq & 15) * 4) * 4,
                 xc + (size_t)cl * (HH * WW) + qq * 4);
        }
        CP_COMMIT();
    }
    for (int i = tid; i < C_IN * 9; i += 256) w1s[i] = ((const float*)g_w1n[p])[i];

    // depthwise decomposition: thread -> 4 channels {2rp,2rp+1,2rp+8,2rp+9}
    // (+ kkp*16), 4 cols n0..n0+3
    const int rp  = tid & 3;
    const int kkp = (tid >> 2) & 1;
    const int nbw = tid >> 3;                // 0..31
    const int n0  = nbw * 4;
    const int rl0 = n0 >> 6;
    const int l0  = n0 & 63;

    float acc[64];
    #pragma unroll
    for (int i = 0; i < 64; i++) acc[i] = 0.f;

    #pragma unroll
    for (int cc = 0; cc < 2; cc++) {
        float* xin = (float*)(smem + (cc ? OFF_X1 : OFF_X0));

        if (cc == 0) { CP_WAIT(1); } else { CP_WAIT(0); }
        __syncthreads();                     // staged data visible; guards BQ reuse

        if (p == 1) {
            #pragma unroll
            for (int i = 0; i < 8; i++) {
                int idx = tid + i * 256;
                int cl = idx >> 6, qq = idx & 63;
                float* pp = xin + xoff(cl, qq >> 4, (qq & 15) * 4);
                float4 v = *(float4*)pp;
                v.x = __logf(v.x + EPS); v.y = __logf(v.y + EPS);
                v.z = __logf(v.z + EPS); v.w = __logf(v.w + EPS);
                *(float4*)pp = v;
            }
            __syncthreads();
        }

        // ---- depthwise 3x3: 4 channels x 4 cols per thread ----
        float dv[4][4];
        #pragma unroll
        for (int i = 0; i < 4; i++)
            #pragma unroll
            for (int j = 0; j < 4; j++) dv[i][j] = 0.f;

        const int dlt[4] = {0, 1, 8, 9};
        #pragma unroll
        for (int c_i = 0; c_i < 4; c_i++) {
            int cl = kkp * 16 + 2 * rp + dlt[c_i];
            const float* wc = w1s + (cc * 32 + cl) * 9;
            float* av = dv[c_i];
            #pragma unroll
            for (int rr = 0; rr < 3; rr++) {
                const float* xr = xin + xoff(cl, rl0 + rr, 0);
                float4 u0 = *(const float4*)(xr + l0);
                float4 u1 = *(const float4*)(xr + l0 + 4);
                float f[8] = {u0.x,u0.y,u0.z,u0.w, u1.x,u1.y,u1.z,u1.w};
                float w0 = wc[rr * 3 + 0], w1v = wc[rr * 3 + 1], w2v = wc[rr * 3 + 2];
                #pragma unroll
                for (int ci = 0; ci < 4; ci++)
                    av[ci] = fmaf(f[ci], w0,
                             fmaf(f[ci + 1], w1v,
                             fmaf(f[ci + 2], w2v, av[ci])));
            }
        }
        // bf16 split + pack quads {h01, l01, h89, l89}; slot = rp
        #pragma unroll
        for (int ci = 0; ci < 4; ci++) {
            int n = n0 + ci;
            float v0 = dv[0][ci], v1 = dv[1][ci], v2 = dv[2][ci], v3 = dv[3][ci];
            float h0 = bf16rn(v0), h1 = bf16rn(v1), h2 = bf16rn(v2), h3 = bf16rn(v3);
            uint32_t h01 = pack_bf(h0, h1);
            uint32_t h89 = pack_bf(h2, h3);
            uint32_t l01 = pack_bf(v0 - h0, v1 - h1);
            uint32_t l89 = pack_bf(v2 - h2, v3 - h3);
            BQ[kkp * 516 + n * 4 + rp] = make_uint4(h01, l01, h89, l89);
        }
        __syncthreads();

        // ---- warp MMA: 2 k-steps x 16 n-tiles x 3 split passes ----
        const float4* wg = &g_w2b[p][cc][0][0][0][0];
        #pragma unroll
        for (int kk = 0; kk < 2; kk++) {
            float4 AH = wg[((kk * 8 + warp) * 32 + lane) * 2 + 0];
            float4 AL = wg[((kk * 8 + warp) * 32 + lane) * 2 + 1];
            uint32_t ah0 = __float_as_uint(AH.x), ah1 = __float_as_uint(AH.y);
            uint32_t ah2 = __float_as_uint(AH.z), ah3 = __float_as_uint(AH.w);
            uint32_t al0 = __float_as_uint(AL.x), al1 = __float_as_uint(AL.y);
            uint32_t al2 = __float_as_uint(AL.z), al3 = __float_as_uint(AL.w);
            const uint4* bq = BQ + kk * 516 + q * 4 + r;
            #pragma unroll
            for (int t = 0; t < 16; t++) {
                uint4 B = bq[t * 32];
                mma_bf16(acc + t * 4, ah0, ah1, ah2, ah3, B.x, B.z);  // hi*hi
                mma_bf16(acc + t * 4, ah0, ah1, ah2, ah3, B.y, B.w);  // hi*lo
                mma_bf16(acc + t * 4, al0, al1, al2, al3, B.x, B.z);  // lo*hi
            }
        }
    }

    // ---- epilogue: direct sector-coalesced stores ----
    float* obase = out + (size_t)(b * 2 + p) * (C_OUT * LTOT) + (size_t)r0 * OY;
    #pragma unroll
    for (int t = 0; t < 16; t++) {
        int colb = (t & 7) * 8 + 2 * r;
        if (colb < OY) {
            int rl = t >> 3;
            float2 v0 = make_float2(acc[t * 4 + 0], acc[t * 4 + 1]);
            float2 v1 = make_float2(acc[t * 4 + 2], acc[t * 4 + 3]);
            if (p == 1) {
                v0.x = __expf(v0.x); v0.y = __expf(v0.y);
                v1.x = __expf(v1.x); v1.y = __expf(v1.y);
            }
            float* addr = obase + rl * OY + colb;
            *(float2*)(addr + (size_t)(m0 + q) * LTOT)     = v0;
            *(float2*)(addr + (size_t)(m0 + q + 8) * LTOT) = v1;
        }
    }
}

// ---------------------------------------------------------------------------
extern "C" void kernel_launch(void* const* d_in, const int* in_sizes, int n_in,
                              void* d_out, int out_size) {
    const float* x  = (const float*)d_in[0];
    const float* w1 = (const float*)d_in[1];
    const float* w2 = (const float*)d_in[2];
    float* out = (float*)d_out;

    prep_weights_kernel<<<1, 256>>>(w1, w2);

    cudaFuncSetAttribute(cce_mma_kernel,
                         cudaFuncAttributeMaxDynamicSharedMemorySize, SMEM_TOTAL);
    dim3 grid(OX / 2, 32, 2);                // (31, 32, 2)
    cce_mma_kernel<<<grid, 256, SMEM_TOTAL>>>(x, out);
}

// round 12
// speedup vs baseline: 2.1151x; 1.0689x over previous
#include <cuda_runtime.h>
#include <cuda_bf16.h>
#include <cstdint>

// ============================================================================
// ComplexConv2Deffangle via warp-level bf16 3-term split MMA (m16n8k16),
// 4-chunk cp.async pipeline, 3 blocks/SM (acc split into 2 halves).
//   path0 (rot): depthwise 3x3 (w1^2/sum)  -> 1x1 (w2^2/sum)
//   path1 (abs): log(x+eps) -> depthwise (w1^2/rowsum) -> 1x1 (w2^2/rowsum) -> exp
// x: (32,2,64,64,64) f32, w1: (64,9), w2: (128,64) -> out: (32,2,128,62,62)
// Per block: D[128 och][128 n] = W[128][64] * V[64][128]; v = hi+lo bf16,
// D = Wh*Vh + Wh*Vl + Wl*Vh.
// ============================================================================

#define EPS 1e-6f
#define C_IN 64
#define C_OUT 128
#define HH 64
#define WW 64
#define OX 62
#define OY 62
#define LTOT (OX * OY)           // 3844

#define XCH 300                  // xin channel stride (floats), 1200 B (16B mult)
#define XRW 68                   // xin row stride (floats), 272 B
#define XBUF 19200               // bytes per xin buffer (16 ch; max off 19,184)

// smem byte offsets
#define OFF_BQ   0               // uint4[4*516]: B quads per chunk     33,024 B
#define OFF_X0   33024           // xin buf0 (16 ch x 4 rows)           19,200 B
#define OFF_X1   52224           // xin buf1                            19,200 B
#define OFF_W1S  71424           // float[64][9]                         2,304 B
#define SMEM_TOTAL 73728         // -> 3 blocks/SM (216 KB / 228 KB)

// A fragments pre-packed for m16n8k16.bf16, hi/lo interleaved:
// g_w2b[p][cc][kk][warp][lane][hl]; chunk g = cc*2 + kk covers ch g*16..+15
__device__ float4 g_w2b[2][2][2][8][32][2];
__device__ float  g_w1n[2][C_IN][9];

// ---------------------------------------------------------------------------
__device__ __forceinline__ uint32_t smem_u32(const void* p) {
    uint32_t a;
    asm("{ .reg .u64 t; cvta.to.shared.u64 t, %1; cvt.u32.u64 %0, t; }"
        : "=r"(a) : "l"(p));
    return a;
}
// returns bf16x2 {upper=hi_e, lower=lo_e}
__device__ __forceinline__ uint32_t pack_bf(float lo_e, float hi_e) {
    uint32_t d;
    asm("cvt.rn.bf16x2.f32 %0, %1, %2;" : "=r"(d) : "f"(hi_e), "f"(lo_e));
    return d;
}
__device__ __forceinline__ float bf16rn(float x) {
    uint32_t d;
    asm("cvt.rn.bf16x2.f32 %0, %1, %1;" : "=r"(d) : "f"(x));
    return __uint_as_float(d << 16);
}
__device__ __forceinline__ void mma_bf16(float* acc, uint32_t a0, uint32_t a1,
                                         uint32_t a2, uint32_t a3,
                                         uint32_t b0, uint32_t b1) {
    asm volatile(
        "mma.sync.aligned.m16n8k16.row.col.f32.bf16.bf16.f32 "
        "{%0,%1,%2,%3}, {%4,%5,%6,%7}, {%8,%9}, {%0,%1,%2,%3};"
        : "+f"(acc[0]), "+f"(acc[1]), "+f"(acc[2]), "+f"(acc[3])
        : "r"(a0), "r"(a1), "r"(a2), "r"(a3), "r"(b0), "r"(b1));
}
__device__ __forceinline__ void cp16(uint32_t dst, const void* src) {
    asm volatile("cp.async.cg.shared.global [%0], [%1], 16;"
                 :: "r"(dst), "l"(src) : "memory");
}
#define CP_COMMIT() asm volatile("cp.async.commit_group;" ::: "memory")
#define CP_WAIT(n)  asm volatile("cp.async.wait_group %0;" :: "n"(n) : "memory")

// xin addressing (floats): channel cl in 0..15, row rr, col f.
// shift (cl>>1)*4 makes 16B-columns a permutation per quarter-warp.
__device__ __forceinline__ int xoff(int cl, int rr, int f) {
    return cl * XCH + (cl >> 1) * 4 + rr * XRW + f;
}

// ---------------------------------------------------------------------------
// Prep kernel: normalize weights, bf16-split, pack mma A fragments.
// ---------------------------------------------------------------------------
__global__ void prep_weights_kernel(const float* __restrict__ w1,
                                    const float* __restrict__ w2) {
    __shared__ float red[256];
    __shared__ float s1_sh, s2_sh;
    __shared__ float s1r[C_IN];
    __shared__ float s2r[C_OUT];
    int tid = threadIdx.x;

    float a = 0.f;
    for (int i = tid; i < C_IN * 9; i += 256) { float t = w1[i]; a += t * t; }
    red[tid] = a; __syncthreads();
    for (int s = 128; s > 0; s >>= 1) { if (tid < s) red[tid] += red[tid + s]; __syncthreads(); }
    if (tid == 0) s1_sh = red[0];
    __syncthreads();

    a = 0.f;
    for (int i = tid; i < C_OUT * C_IN; i += 256) { float t = w2[i]; a += t * t; }
    red[tid] = a; __syncthreads();
    for (int s = 128; s > 0; s >>= 1) { if (tid < s) red[tid] += red[tid + s]; __syncthreads(); }
    if (tid == 0) s2_sh = red[0];

    if (tid < C_IN) {
        float s = 0.f;
        for (int k = 0; k < 9; k++) { float t = w1[tid * 9 + k]; s += t * t; }
        s1r[tid] = s;
    }
    if (tid < C_OUT) {
        float s = 0.f;
        for (int c = 0; c < C_IN; c++) { float t = w2[tid * C_IN + c]; s += t * t; }
        s2r[tid] = s;
    }
    __syncthreads();

    float inv_s1 = 1.f / s1_sh;
    float inv_s2 = 1.f / s2_sh;

    for (int i = tid; i < C_IN * 9; i += 256) {
        int c = i / 9;
        float t = w1[i]; float t2 = t * t;
        ((float*)g_w1n[0])[i] = t2 * inv_s1;
        ((float*)g_w1n[1])[i] = t2 / s1r[c];
    }

    // A fragments: j indexes (p, cc, kk, warp, lane)
    float4* flat = (float4*)g_w2b;
    for (int j = tid; j < 2048; j += 256) {
        int lane = j & 31;
        int wq   = (j >> 5) & 7;
        int kk   = (j >> 8) & 1;
        int cc   = (j >> 9) & 1;
        int p    = j >> 10;
        int qq = lane >> 2, rr2 = lane & 3;
        int cb = cc * 32 + kk * 16 + 2 * rr2;
        int ms[2] = {wq * 16 + qq, wq * 16 + qq + 8};
        uint32_t ah[4], al[4];
        #pragma unroll
        for (int i = 0; i < 4; i++) {
            int m  = ms[i & 1];
            int c0 = cb + (i >> 1) * 8;
            float t0 = w2[m * C_IN + c0];
            float t1 = w2[m * C_IN + c0 + 1];
            float v0 = (p == 0) ? t0 * t0 * inv_s2 : t0 * t0 / s2r[m];
            float v1 = (p == 0) ? t1 * t1 * inv_s2 : t1 * t1 / s2r[m];
            float h0 = bf16rn(v0), h1 = bf16rn(v1);
            ah[i] = pack_bf(h0, h1);           // lower = k even
            al[i] = pack_bf(v0 - h0, v1 - h1);
        }
        flat[j * 2 + 0] = make_float4(__uint_as_float(ah[0]), __uint_as_float(ah[1]),
                                      __uint_as_float(ah[2]), __uint_as_float(ah[3]));
        flat[j * 2 + 1] = make_float4(__uint_as_float(al[0]), __uint_as_float(al[1]),
                                      __uint_as_float(al[2]), __uint_as_float(al[3]));
    }
}

// ---------------------------------------------------------------------------
// Main kernel: grid (31 row-pairs, 32 batch, 2 path), 256 threads, 3 blk/SM.
// ---------------------------------------------------------------------------
__global__ __launch_bounds__(256, 3)
void cce_mma_kernel(const float* __restrict__ x, float* __restrict__ out) {
    extern __shared__ char smem[];
    const uint32_t sb = smem_u32(smem);
    uint4*  BQ4 = (uint4*)(smem + OFF_BQ);
    uint2*  BQ2 = (uint2*)(smem + OFF_BQ);
    float*  w1s = (float*)(smem + OFF_W1S);

    const int tid  = threadIdx.x;
    const int warp = tid >> 5;
    const int lane = tid & 31;
    const int q    = lane >> 2;              // groupID
    const int r    = lane & 3;               // threadInGroup
    const int m0   = warp * 16;              // och tile base
    const int r0   = blockIdx.x * 2;
    const int b    = blockIdx.y;
    const int p    = blockIdx.z;

    const float* xbase = x + (size_t)(b * 2 + p) * (C_IN * HH * WW) + r0 * WW;

    // ---- stage helper: issue cp.async for chunk g into buffer (g&1) ----
    auto issue_chunk = [&](int g) {
        const uint32_t xo = sb + ((g & 1) ? OFF_X1 : OFF_X0);
        const float* xc = xbase + (size_t)(g * 16) * (HH * WW);
        #pragma unroll
        for (int i = 0; i < 4; i++) {
            int idx = tid + i * 256;         // 0..1023 float4
            int cl = idx >> 6, qq = idx & 63;
            cp16(xo + (uint32_t)xoff(cl, qq >> 4, (qq & 15) * 4) * 4,
                 xc + (size_t)cl * (HH * WW) + qq * 4);
        }
        CP_COMMIT();
    };

    issue_chunk(0);
    issue_chunk(1);
    for (int i = tid; i < C_IN * 9; i += 256) w1s[i] = ((const float*)g_w1n[p])[i];

    // dw decomposition: hp = ch-offset half {0,8}, rp = r-slot, 4 cols
    const int hp  = tid & 1;
    const int rp  = (tid >> 1) & 3;
    const int nb  = tid >> 3;                // 0..31
    const int n0  = nb * 4;
    const int rl0 = n0 >> 6;
    const int l0  = n0 & 63;                 // 4-aligned

    // ========== staging + depthwise, 4 chunks of 16 channels ==========
    #pragma unroll
    for (int g = 0; g < 4; g++) {
        float* xin = (float*)(smem + ((g & 1) ? OFF_X1 : OFF_X0));

        if (g < 3) { CP_WAIT(1); } else { CP_WAIT(0); }
        __syncthreads();

        if (p == 1) {
            #pragma unroll
            for (int i = 0; i < 4; i++) {
                int idx = tid + i * 256;
                int cl = idx >> 6, qq = idx & 63;
                float* pp = xin + xoff(cl, qq >> 4, (qq & 15) * 4);
                float4 v = *(float4*)pp;
                v.x = __logf(v.x + EPS); v.y = __logf(v.y + EPS);
                v.z = __logf(v.z + EPS); v.w = __logf(v.w + EPS);
                *(float4*)pp = v;
            }
            __syncthreads();
        }

        // depthwise 3x3: 2 channels x 4 cols per thread
        float dv[2][4];
        #pragma unroll
        for (int i = 0; i < 2; i++)
            #pragma unroll
            for (int j = 0; j < 4; j++) dv[i][j] = 0.f;

        #pragma unroll
        for (int ch2 = 0; ch2 < 2; ch2++) {
            int cl = 2 * rp + 8 * hp + ch2;
            const float* wc = w1s + (g * 16 + cl) * 9;
            float* av = dv[ch2];
            #pragma unroll
            for (int rr = 0; rr < 3; rr++) {
                const float* xr = xin + xoff(cl, rl0 + rr, 0);
                float4 u0 = *(const float4*)(xr + l0);
                float4 u1 = *(const float4*)(xr + l0 + 4);
                float f[8] = {u0.x,u0.y,u0.z,u0.w, u1.x,u1.y,u1.z,u1.w};
                float w0 = wc[rr * 3 + 0], w1v = wc[rr * 3 + 1], w2v = wc[rr * 3 + 2];
                #pragma unroll
                for (int ci = 0; ci < 4; ci++)
                    av[ci] = fmaf(f[ci], w0,
                             fmaf(f[ci + 1], w1v,
                             fmaf(f[ci + 2], w2v, av[ci])));
            }
        }
        // bf16 split + store half-quads {h01, l01} (hp selects quad half)
        #pragma unroll
        for (int ci = 0; ci < 4; ci++) {
            int n = n0 + ci;
            float v0 = dv[0][ci], v1 = dv[1][ci];
            float h0 = bf16rn(v0), h1 = bf16rn(v1);
            BQ2[(g * 516 + n * 4 + rp) * 2 + hp] =
                make_uint2(pack_bf(h0, h1), pack_bf(v0 - h0, v1 - h1));
        }
        __syncthreads();                     // buffer free + BQ[g] visible

        if (g < 2) issue_chunk(g + 2);
    }

    // ========== MMA in 2 halves (acc=32), epilogue per half ==========
    float* obase = out + (size_t)(b * 2 + p) * (C_OUT * LTOT) + (size_t)r0 * OY;
    #pragma unroll
    for (int half = 0; half < 2; half++) {
        float acc[32];
        #pragma unroll
        for (int i = 0; i < 32; i++) acc[i] = 0.f;

        #pragma unroll
        for (int g = 0; g < 4; g++) {
            const float4* wg = &g_w2b[p][g >> 1][g & 1][warp][lane][0];
            float4 AH = wg[0];
            float4 AL = wg[1];
            uint32_t ah0 = __float_as_uint(AH.x), ah1 = __float_as_uint(AH.y);
            uint32_t ah2 = __float_as_uint(AH.z), ah3 = __float_as_uint(AH.w);
            uint32_t al0 = __float_as_uint(AL.x), al1 = __float_as_uint(AL.y);
            uint32_t al2 = __float_as_uint(AL.z), al3 = __float_as_uint(AL.w);
            const uint4* bq = BQ4 + g * 516 + (half * 8) * 32 + q * 4 + r;
            #pragma unroll
            for (int t = 0; t < 8; t++) {
                uint4 B = bq[t * 32];
                mma_bf16(acc + t * 4, ah0, ah1, ah2, ah3, B.x, B.z);  // hi*hi
                mma_bf16(acc + t * 4, ah0, ah1, ah2, ah3, B.y, B.w);  // hi*lo
                mma_bf16(acc + t * 4, al0, al1, al2, al3, B.x, B.z);  // lo*hi
            }
        }

        // epilogue: out row rl = half, direct sector-coalesced stores
        #pragma unroll
        for (int t = 0; t < 8; t++) {
            int colb = t * 8 + 2 * r;
            if (colb < OY) {
                float2 v0 = make_float2(acc[t * 4 + 0], acc[t * 4 + 1]);
                float2 v1 = make_float2(acc[t * 4 + 2], acc[t * 4 + 3]);
                if (p == 1) {
                    v0.x = __expf(v0.x); v0.y = __expf(v0.y);
                    v1.x = __expf(v1.x); v1.y = __expf(v1.y);
                }
                float* addr = obase + half * OY + colb;
                *(float2*)(addr + (size_t)(m0 + q) * LTOT)     = v0;
                *(float2*)(addr + (size_t)(m0 + q + 8) * LTOT) = v1;
            }
        }
    }
}

// ---------------------------------------------------------------------------
extern "C" void kernel_launch(void* const* d_in, const int* in_sizes, int n_in,
                              void* d_out, int out_size) {
    const float* x  = (const float*)d_in[0];
    const float* w1 = (const float*)d_in[1];
    const float* w2 = (const float*)d_in[2];
    float* out = (float*)d_out;

    prep_weights_kernel<<<1, 256>>>(w1, w2);

    cudaFuncSetAttribute(cce_mma_kernel,
                         cudaFuncAttributeMaxDynamicSharedMemorySize, SMEM_TOTAL);
    dim3 grid(OX / 2, 32, 2);                // (31, 32, 2)
    cce_mma_kernel<<<grid, 256, SMEM_TOTAL>>>(x, out);
}